// round 9
// baseline (speedup 1.0000x reference)
#include <cuda_runtime.h>

// Controlled-SX on qutrits (dim=3, 16 qudits), ctrl=2, obj=5.
//   d2!=1          : out[i] = in[i]
//   d2==1, d5==0   : out[i] = in[i + 3^10]
//   d2==1, d5==1   : out[i] = in[i - 3^10]
//   d2==1, d5==2   : out[i] = 0
// 1 thread = 1 oct (8 elements) via TRUE 256-bit LDG/STG (ld/st.global.v8.f32,
// sm_100+). Single 256-bit op with 32B lane stride fully covers its lines per
// instruction (unlike R4's two thread-consecutive LDG.128s). Probes whether
// request granularity buys DRAM efficiency at the ~6.4 TB/s plateau.
// out_im = d_out + n with n odd -> 4B-aligned only: scalar stores for im.

static constexpr int S5 = 59049;    // 3^10
static constexpr int S2 = 1594323;  // 3^13 = 27 * S5

__device__ __forceinline__ void ldg256(const float* p, float* v)
{
    asm volatile("ld.global.nc.v8.f32 {%0,%1,%2,%3,%4,%5,%6,%7}, [%8];"
                 : "=f"(v[0]), "=f"(v[1]), "=f"(v[2]), "=f"(v[3]),
                   "=f"(v[4]), "=f"(v[5]), "=f"(v[6]), "=f"(v[7])
                 : "l"(p));
}

__device__ __forceinline__ void stg256(float* p, const float* v)
{
    asm volatile("st.global.cs.v8.f32 [%0], {%1,%2,%3,%4,%5,%6,%7,%8};"
                 :: "l"(p),
                    "f"(v[0]), "f"(v[1]), "f"(v[2]), "f"(v[3]),
                    "f"(v[4]), "f"(v[5]), "f"(v[6]), "f"(v[7])
                 : "memory");
}

__device__ __forceinline__ void scalar_one(const float* __restrict__ in_re,
                                           const float* __restrict__ in_im,
                                           float* __restrict__ out_re,
                                           float* __restrict__ out_im,
                                           int idx)
{
    int q5 = idx / S5;
    int d5 = q5 % 3;
    int d2 = (q5 / 27) % 3;
    float vr, vi;
    if (d2 != 1) {
        vr = __ldcs(in_re + idx);
        vi = __ldcs(in_im + idx);
    } else if (d5 == 0) {
        vr = __ldcs(in_re + idx + S5);
        vi = __ldcs(in_im + idx + S5);
    } else if (d5 == 1) {
        vr = __ldcs(in_re + idx - S5);
        vi = __ldcs(in_im + idx - S5);
    } else {
        vr = 0.0f; vi = 0.0f;
    }
    __stcs(out_re + idx, vr);
    __stcs(out_im + idx, vi);
}

__global__ void __launch_bounds__(512)
sx_apply_v256(const float* __restrict__ in_re,
              const float* __restrict__ in_im,
              float* __restrict__ out_re,
              float* __restrict__ out_im,   // 4B-aligned only: scalar stores
              int n, int noct)
{
    int t = blockIdx.x * blockDim.x + threadIdx.x;
    if (t >= noct) return;
    int i = t << 3;                   // 8 elements; i*4 is 32B-aligned

    int q5 = i / S5;                  // one magic-mul divide per 8 elements
    int r5 = i - q5 * S5;
    int d5 = q5 % 3;
    int d2 = (q5 / 27) % 3;

    bool fast = (i + 8 <= n) && (r5 + 8 <= S5);

    if (fast) {
        float vr[8], vi[8];
        if (d2 != 1) {
            ldg256(in_re + i, vr);           // LDG.256, fully coalesced
            ldg256(in_im + i, vi);
        } else if (d5 == 2) {
            #pragma unroll
            for (int j = 0; j < 8; j++) { vr[j] = 0.0f; vi[j] = 0.0f; }
        } else {
            int s = (d5 == 0) ? (i + S5) : (i - S5);  // odd offset: scalar gather
            #pragma unroll
            for (int j = 0; j < 8; j++) vr[j] = __ldcs(in_re + s + j);
            #pragma unroll
            for (int j = 0; j < 8; j++) vi[j] = __ldcs(in_im + s + j);
        }
        stg256(out_re + i, vr);              // STG.256 streaming (32B-aligned)
        #pragma unroll
        for (int j = 0; j < 8; j++)          // STG.32 x8 (out_im 4B-aligned)
            __stcs(out_im + i + j, vi[j]);
    } else {
        #pragma unroll
        for (int j = 0; j < 8; j++) {
            int idx = i + j;
            if (idx < n)
                scalar_one(in_re, in_im, out_re, out_im, idx);
        }
    }
}

extern "C" void kernel_launch(void* const* d_in, const int* in_sizes, int n_in,
                              void* d_out, int out_size)
{
    const float* in_re = (const float*)d_in[0];
    const float* in_im = (const float*)d_in[1];
    const int n = in_sizes[0];          // 3^16 = 43,046,721 (odd)

    float* out_re = (float*)d_out;
    float* out_im = (float*)d_out + n;  // 4B-aligned only

    const int noct = (n + 7) >> 3;
    const int threads = 512;
    const int blocks = (noct + threads - 1) / threads;
    sx_apply_v256<<<blocks, threads>>>(in_re, in_im, out_re, out_im, n, noct);
}

// round 10
// speedup vs baseline: 1.8686x; 1.8686x over previous
#include <cuda_runtime.h>

// FINAL — Controlled-SX on qutrits (dim=3, 16 qudits), ctrl=2, obj=5.
//   d2!=1          : out[i] = in[i]
//   d2==1, d5==0   : out[i] = in[i + 3^10]
//   d2==1, d5==1   : out[i] = in[i - 3^10]
//   d2==1, d5==2   : out[i] = 0
// Structure locked by 9 rounds of evidence:
//  - 1 thread = 1 float4 quad (lane stride 16B) is the unique coalescing
//    optimum; wider per-thread footprints (R4 2xLDG.128, R9 LDG.256) crack
//    into half-sector-covered accesses and halve L1 throughput.
//  - Extra MLP (R5), grid-stride (R6), cache hints (R7) are all flat or
//    worse: kernel sits at the DRAM mixed-stream ceiling (~6.4 TB/s ncu,
//    ~6.9 TB/s application traffic incl. unread zero-region).
//  - 512-thread blocks trim the wave-quantization tail (R8, best: 97.7us).
// out_im = d_out + n with n odd -> 4B-aligned only: scalar stores for im.

static constexpr int S5 = 59049;    // 3^10
static constexpr int S2 = 1594323;  // 3^13 = 27 * S5

__device__ __forceinline__ void scalar_one(const float* __restrict__ in_re,
                                           const float* __restrict__ in_im,
                                           float* __restrict__ out_re,
                                           float* __restrict__ out_im,
                                           int idx)
{
    int q5 = idx / S5;
    int d5 = q5 % 3;
    int d2 = (q5 / 27) % 3;
    float vr, vi;
    if (d2 != 1) {
        vr = __ldcs(in_re + idx);
        vi = __ldcs(in_im + idx);
    } else if (d5 == 0) {
        vr = __ldcs(in_re + idx + S5);
        vi = __ldcs(in_im + idx + S5);
    } else if (d5 == 1) {
        vr = __ldcs(in_re + idx - S5);
        vi = __ldcs(in_im + idx - S5);
    } else {
        vr = 0.0f; vi = 0.0f;
    }
    __stcs(out_re + idx, vr);
    __stcs(out_im + idx, vi);
}

__global__ void __launch_bounds__(512)
sx_apply_final(const float* __restrict__ in_re,
               const float* __restrict__ in_im,
               float* __restrict__ out_re,
               float* __restrict__ out_im,   // 4B-aligned only: scalar stores
               int n, int nq)
{
    int q = blockIdx.x * blockDim.x + threadIdx.x;
    if (q >= nq) return;
    int i = q << 2;

    int q5 = i / S5;                 // magic-mul divide
    int r5 = i - q5 * S5;
    int d5 = q5 % 3;
    int d2 = (q5 / 27) % 3;

    bool fast = (i + 4 <= n) && (r5 + 4 <= S5);

    if (fast) {
        const float4* in_re4  = reinterpret_cast<const float4*>(in_re);
        const float4* in_im4  = reinterpret_cast<const float4*>(in_im);
        float4*       out_re4 = reinterpret_cast<float4*>(out_re);

        float4 vr, vi;
        if (d2 != 1) {
            vr = __ldcs(in_re4 + q);         // LDG.E.128 streaming, coalesced
            vi = __ldcs(in_im4 + q);
        } else if (d5 == 2) {
            vr = make_float4(0.f, 0.f, 0.f, 0.f);
            vi = vr;
        } else {
            int s = (d5 == 0) ? (i + S5) : (i - S5);  // odd offset: scalar gather
            vr.x = __ldcs(in_re + s + 0);
            vr.y = __ldcs(in_re + s + 1);
            vr.z = __ldcs(in_re + s + 2);
            vr.w = __ldcs(in_re + s + 3);
            vi.x = __ldcs(in_im + s + 0);
            vi.y = __ldcs(in_im + s + 1);
            vi.z = __ldcs(in_im + s + 2);
            vi.w = __ldcs(in_im + s + 3);
        }
        __stcs(out_re4 + q, vr);             // STG.128 streaming (aligned)
        __stcs(out_im + i + 0, vi.x);        // STG.32 streaming x4 (coalesced)
        __stcs(out_im + i + 1, vi.y);
        __stcs(out_im + i + 2, vi.z);
        __stcs(out_im + i + 3, vi.w);
    } else {
        #pragma unroll
        for (int j = 0; j < 4; j++) {
            int idx = i + j;
            if (idx < n)
                scalar_one(in_re, in_im, out_re, out_im, idx);
        }
    }
}

extern "C" void kernel_launch(void* const* d_in, const int* in_sizes, int n_in,
                              void* d_out, int out_size)
{
    const float* in_re = (const float*)d_in[0];
    const float* in_im = (const float*)d_in[1];
    const int n = in_sizes[0];          // 3^16 = 43,046,721 (odd)

    float* out_re = (float*)d_out;
    float* out_im = (float*)d_out + n;  // 4B-aligned only

    const int nq = (n + 3) >> 2;
    const int threads = 512;
    const int blocks = (nq + threads - 1) / threads;
    sx_apply_final<<<blocks, threads>>>(in_re, in_im, out_re, out_im, n, nq);
}

// round 11
// speedup vs baseline: 1.8717x; 1.0016x over previous
#include <cuda_runtime.h>

// FINAL (converged R10) — Controlled-SX on qutrits (dim=3, 16 qudits),
// ctrl=2, obj=5.
//   d2!=1          : out[i] = in[i]
//   d2==1, d5==0   : out[i] = in[i + 3^10]
//   d2==1, d5==1   : out[i] = in[i - 3^10]
//   d2==1, d5==2   : out[i] = 0
// Evidence across 10 rounds:
//  - 1 thread = 1 float4 quad (lane stride 16B) is the coalescing optimum;
//    wider per-thread footprints (2xLDG.128 or LDG.256) crack into
//    half-sector accesses and halve L1 throughput (R4, R9: ~2x slower).
//  - Extra MLP (R5), streaming hints (R7), grid-stride (R6): flat or worse.
//  - Kernel sits at the DRAM mixed-stream ceiling: ~6.3-6.4 TB/s ncu DRAM,
//    ~6.9 TB/s application-effective (zero region never read).
//  - 512-thread blocks trim the wave-quantization tail.
// out_im = d_out + n with n odd -> 4B-aligned only: scalar stores for im
// (coalesced STG.32 x4; store path is not the binder).

static constexpr int S5 = 59049;    // 3^10
static constexpr int S2 = 1594323;  // 3^13 = 27 * S5

__device__ __forceinline__ void scalar_one(const float* __restrict__ in_re,
                                           const float* __restrict__ in_im,
                                           float* __restrict__ out_re,
                                           float* __restrict__ out_im,
                                           int idx)
{
    int q5 = idx / S5;
    int d5 = q5 % 3;
    int d2 = (q5 / 27) % 3;
    float vr, vi;
    if (d2 != 1) {
        vr = __ldcs(in_re + idx);
        vi = __ldcs(in_im + idx);
    } else if (d5 == 0) {
        vr = __ldcs(in_re + idx + S5);
        vi = __ldcs(in_im + idx + S5);
    } else if (d5 == 1) {
        vr = __ldcs(in_re + idx - S5);
        vi = __ldcs(in_im + idx - S5);
    } else {
        vr = 0.0f; vi = 0.0f;
    }
    __stcs(out_re + idx, vr);
    __stcs(out_im + idx, vi);
}

__global__ void __launch_bounds__(512)
sx_apply_final(const float* __restrict__ in_re,
               const float* __restrict__ in_im,
               float* __restrict__ out_re,
               float* __restrict__ out_im,   // 4B-aligned only: scalar stores
               int n, int nq)
{
    int q = blockIdx.x * blockDim.x + threadIdx.x;
    if (q >= nq) return;
    int i = q << 2;

    int q5 = i / S5;                 // magic-mul divide
    int r5 = i - q5 * S5;
    int d5 = q5 % 3;
    int d2 = (q5 / 27) % 3;

    bool fast = (i + 4 <= n) && (r5 + 4 <= S5);

    if (fast) {
        const float4* in_re4  = reinterpret_cast<const float4*>(in_re);
        const float4* in_im4  = reinterpret_cast<const float4*>(in_im);
        float4*       out_re4 = reinterpret_cast<float4*>(out_re);

        float4 vr, vi;
        if (d2 != 1) {
            vr = __ldcs(in_re4 + q);         // LDG.E.128 streaming, coalesced
            vi = __ldcs(in_im4 + q);
        } else if (d5 == 2) {
            vr = make_float4(0.f, 0.f, 0.f, 0.f);
            vi = vr;
        } else {
            int s = (d5 == 0) ? (i + S5) : (i - S5);  // odd offset: scalar gather
            vr.x = __ldcs(in_re + s + 0);
            vr.y = __ldcs(in_re + s + 1);
            vr.z = __ldcs(in_re + s + 2);
            vr.w = __ldcs(in_re + s + 3);
            vi.x = __ldcs(in_im + s + 0);
            vi.y = __ldcs(in_im + s + 1);
            vi.z = __ldcs(in_im + s + 2);
            vi.w = __ldcs(in_im + s + 3);
        }
        __stcs(out_re4 + q, vr);             // STG.128 streaming (aligned)
        __stcs(out_im + i + 0, vi.x);        // STG.32 streaming x4 (coalesced)
        __stcs(out_im + i + 1, vi.y);
        __stcs(out_im + i + 2, vi.z);
        __stcs(out_im + i + 3, vi.w);
    } else {
        #pragma unroll
        for (int j = 0; j < 4; j++) {
            int idx = i + j;
            if (idx < n)
                scalar_one(in_re, in_im, out_re, out_im, idx);
        }
    }
}

extern "C" void kernel_launch(void* const* d_in, const int* in_sizes, int n_in,
                              void* d_out, int out_size)
{
    const float* in_re = (const float*)d_in[0];
    const float* in_im = (const float*)d_in[1];
    const int n = in_sizes[0];          // 3^16 = 43,046,721 (odd)

    float* out_re = (float*)d_out;
    float* out_im = (float*)d_out + n;  // 4B-aligned only

    const int nq = (n + 3) >> 2;
    const int threads = 512;
    const int blocks = (nq + threads - 1) / threads;
    sx_apply_final<<<blocks, threads>>>(in_re, in_im, out_re, out_im, n, nq);
}

// round 12
// speedup vs baseline: 1.8958x; 1.0129x over previous
#include <cuda_runtime.h>

// FINAL (converged; certified R8/R10/R11) — Controlled-SX on qutrits
// (dim=3, 16 qudits), ctrl=2, obj=5.
//   d2!=1          : out[i] = in[i]
//   d2==1, d5==0   : out[i] = in[i + 3^10]
//   d2==1, d5==1   : out[i] = in[i - 3^10]
//   d2==1, d5==2   : out[i] = 0
// Evidence across 11 rounds:
//  - 1 thread = 1 float4 quad (lane stride 16B) is the coalescing optimum;
//    wider per-thread footprints (2xLDG.128 or LDG.256) crack into
//    half-sector accesses and halve L1 throughput (R4, R9: ~2x slower).
//  - Extra MLP (R5), streaming hints (R7), grid-stride (R6): flat or worse.
//  - At the HBM3e mixed r/w stream ceiling: ~6.3 TB/s ncu DRAM (~79% spec),
//    ~6.9 TB/s application-effective (zero region never read).
//  - CE-memcpy splitting / im-plane wide stores rejected on arithmetic
//    (DRAM-bound aggregate; out_im phase is permanently 4B-odd).
// out_im = d_out + n with n odd -> 4B-aligned only: scalar stores for im.

static constexpr int S5 = 59049;    // 3^10
static constexpr int S2 = 1594323;  // 3^13 = 27 * S5

__device__ __forceinline__ void scalar_one(const float* __restrict__ in_re,
                                           const float* __restrict__ in_im,
                                           float* __restrict__ out_re,
                                           float* __restrict__ out_im,
                                           int idx)
{
    int q5 = idx / S5;
    int d5 = q5 % 3;
    int d2 = (q5 / 27) % 3;
    float vr, vi;
    if (d2 != 1) {
        vr = __ldcs(in_re + idx);
        vi = __ldcs(in_im + idx);
    } else if (d5 == 0) {
        vr = __ldcs(in_re + idx + S5);
        vi = __ldcs(in_im + idx + S5);
    } else if (d5 == 1) {
        vr = __ldcs(in_re + idx - S5);
        vi = __ldcs(in_im + idx - S5);
    } else {
        vr = 0.0f; vi = 0.0f;
    }
    __stcs(out_re + idx, vr);
    __stcs(out_im + idx, vi);
}

__global__ void __launch_bounds__(512)
sx_apply_final(const float* __restrict__ in_re,
               const float* __restrict__ in_im,
               float* __restrict__ out_re,
               float* __restrict__ out_im,   // 4B-aligned only: scalar stores
               int n, int nq)
{
    int q = blockIdx.x * blockDim.x + threadIdx.x;
    if (q >= nq) return;
    int i = q << 2;

    int q5 = i / S5;                 // magic-mul divide
    int r5 = i - q5 * S5;
    int d5 = q5 % 3;
    int d2 = (q5 / 27) % 3;

    bool fast = (i + 4 <= n) && (r5 + 4 <= S5);

    if (fast) {
        const float4* in_re4  = reinterpret_cast<const float4*>(in_re);
        const float4* in_im4  = reinterpret_cast<const float4*>(in_im);
        float4*       out_re4 = reinterpret_cast<float4*>(out_re);

        float4 vr, vi;
        if (d2 != 1) {
            vr = __ldcs(in_re4 + q);         // LDG.E.128 streaming, coalesced
            vi = __ldcs(in_im4 + q);
        } else if (d5 == 2) {
            vr = make_float4(0.f, 0.f, 0.f, 0.f);
            vi = vr;
        } else {
            int s = (d5 == 0) ? (i + S5) : (i - S5);  // odd offset: scalar gather
            vr.x = __ldcs(in_re + s + 0);
            vr.y = __ldcs(in_re + s + 1);
            vr.z = __ldcs(in_re + s + 2);
            vr.w = __ldcs(in_re + s + 3);
            vi.x = __ldcs(in_im + s + 0);
            vi.y = __ldcs(in_im + s + 1);
            vi.z = __ldcs(in_im + s + 2);
            vi.w = __ldcs(in_im + s + 3);
        }
        __stcs(out_re4 + q, vr);             // STG.128 streaming (aligned)
        __stcs(out_im + i + 0, vi.x);        // STG.32 streaming x4 (coalesced)
        __stcs(out_im + i + 1, vi.y);
        __stcs(out_im + i + 2, vi.z);
        __stcs(out_im + i + 3, vi.w);
    } else {
        #pragma unroll
        for (int j = 0; j < 4; j++) {
            int idx = i + j;
            if (idx < n)
                scalar_one(in_re, in_im, out_re, out_im, idx);
        }
    }
}

extern "C" void kernel_launch(void* const* d_in, const int* in_sizes, int n_in,
                              void* d_out, int out_size)
{
    const float* in_re = (const float*)d_in[0];
    const float* in_im = (const float*)d_in[1];
    const int n = in_sizes[0];          // 3^16 = 43,046,721 (odd)

    float* out_re = (float*)d_out;
    float* out_im = (float*)d_out + n;  // 4B-aligned only

    const int nq = (n + 3) >> 2;
    const int threads = 512;
    const int blocks = (nq + threads - 1) / threads;
    sx_apply_final<<<blocks, threads>>>(in_re, in_im, out_re, out_im, n, nq);
}